// round 1
// baseline (speedup 1.0000x reference)
#include <cuda_runtime.h>
#include <cstdint>

#define NV 8192
#define DV 32
#define TV 12
#define RV 192   /* B*C*T = 2*8*12 */

typedef unsigned long long ull;

// ---- device scratch (statically allocated; no cudaMalloc anywhere) ----
__device__ float g_core[DV * DV];                 // [e][f]
__device__ float g_a[NV * DV];                    // nodevec1 @ core
__device__ float g_P[(size_t)NV * NV];            // exp(relu(adp)) fp32, 256 MB
__device__ float g_rspart[8 * NV];                // rowsum partials per m-strip
__device__ float g_xs[NV * RV];                   // x transposed [n][bct] / rowsum[n]
__device__ float g_part[4ULL * RV * NV];          // split-K partials, 25 MB

// ---- f32x2 packed-FMA helpers (FFMA2; 2x fp32 throughput on sm_103a) ----
__device__ __forceinline__ ull pack2(float lo, float hi) {
    ull r; asm("mov.b64 %0, {%1,%2};" : "=l"(r) : "f"(lo), "f"(hi)); return r;
}
__device__ __forceinline__ void fma2(ull &acc, ull a, ull b) {
    asm("fma.rn.f32x2 %0, %1, %2, %0;" : "+l"(acc) : "l"(a), "l"(b));
}
__device__ __forceinline__ float2 unpack2(ull v) {
    float lo, hi; asm("mov.b64 {%0,%1}, %2;" : "=f"(lo), "=f"(hi) : "l"(v));
    return make_float2(lo, hi);
}

// ========== K1a: core[e][f] = sum_d tv[d] * k[d][e][f]  (1 CTA, 1024 thr) ==========
__global__ void k_core(const float* __restrict__ timevec,
                       const float* __restrict__ kk,
                       const int* __restrict__ tind) {
    int e = threadIdx.x >> 5, f = threadIdx.x & 31;
    int ti = tind[0];
    float s = 0.f;
#pragma unroll
    for (int d = 0; d < DV; ++d)
        s += timevec[ti * DV + d] * kk[(d * DV + e) * DV + f];
    g_core[e * DV + f] = s;
}

// ========== K1b: a[n][f] = sum_e nodevec1[n][e] * core[e][f] ==========
__global__ void k_amat(const float* __restrict__ nv1) {
    __shared__ float sc[DV * DV];
    int tid = threadIdx.x;
    for (int i = tid; i < DV * DV; i += 256) sc[i] = g_core[i];
    __syncthreads();
    int n = blockIdx.x * 8 + (tid >> 5);
    int f = tid & 31;
    float s = 0.f;
#pragma unroll
    for (int e = 0; e < DV; ++e) s += nv1[n * DV + e] * sc[e * DV + f];
    g_a[n * DV + f] = s;
}

// ========== K2: P[n][m] = exp(relu(a_n . nodevec2_m)), rowsum partials ==========
// grid (8 m-strips, 64 row-blocks), 256 threads.
// Thread tile 8 rows x 4 cols per 64-col chunk; f32x2 packing along D (dot products).
__global__ __launch_bounds__(256) void k_padj(const float* __restrict__ nv2) {
    __shared__ float sA[128 * 34];       // a rows, padded (8B-aligned rows, no bank conflicts)
    __shared__ ull   sB[16 * 66];        // nodevec2 chunk as k2-major f32x2 pairs

    int tid = threadIdx.x;
    int row0 = blockIdx.y * 128;
    int strip = blockIdx.x;              // 0..7, 1024 cols each

    for (int idx = tid; idx < 128 * 32; idx += 256) {
        int r = idx >> 5, c = idx & 31;
        sA[r * 34 + c] = g_a[(row0 + r) * DV + c];
    }

    int ty = tid >> 4;                   // 0..15 -> 8 rows each
    int tx = tid & 15;                   // 0..15 -> cols j*16+tx
    float rs[8];
#pragma unroll
    for (int i = 0; i < 8; ++i) rs[i] = 0.f;

    for (int mc = 0; mc < 16; ++mc) {
        int m0 = strip * 1024 + mc * 64;
        __syncthreads();                 // prev chunk's consumers done (also covers sA fill)
        for (int idx = tid; idx < 16 * 64; idx += 256) {
            int m = idx >> 4, k2 = idx & 15;
            sB[k2 * 66 + m] = *(const ull*)&nv2[(size_t)(m0 + m) * DV + 2 * k2];
        }
        __syncthreads();

        ull acc[8][4];
#pragma unroll
        for (int i = 0; i < 8; ++i)
#pragma unroll
            for (int j = 0; j < 4; ++j) acc[i][j] = 0ull;

#pragma unroll
        for (int k2 = 0; k2 < 16; ++k2) {
            ull bv[4], av[8];
#pragma unroll
            for (int j = 0; j < 4; ++j) bv[j] = sB[k2 * 66 + j * 16 + tx];
#pragma unroll
            for (int i = 0; i < 8; ++i)
                av[i] = *(const ull*)&sA[(ty * 8 + i) * 34 + 2 * k2];
#pragma unroll
            for (int i = 0; i < 8; ++i)
#pragma unroll
                for (int j = 0; j < 4; ++j) fma2(acc[i][j], av[i], bv[j]);
        }

#pragma unroll
        for (int i = 0; i < 8; ++i) {
            int n = row0 + ty * 8 + i;
#pragma unroll
            for (int j = 0; j < 4; ++j) {
                float2 h = unpack2(acc[i][j]);
                float v = fmaxf(h.x + h.y, 0.f);
                float p = __expf(v);
                g_P[(size_t)n * NV + m0 + j * 16 + tx] = p;
                rs[i] += p;
            }
        }
    }

    // reduce row partials over the 16 tx lanes (fixed order -> deterministic)
#pragma unroll
    for (int i = 0; i < 8; ++i) {
        float v = rs[i];
#pragma unroll
        for (int off = 8; off >= 1; off >>= 1)
            v += __shfl_xor_sync(0xffffffffu, v, off, 16);
        if (tx == 0) g_rspart[strip * NV + row0 + ty * 8 + i] = v;
    }
}

// ========== K3: xs[n][bct] = x[b][c][n][t] / rowsum[n]  (grid NV, 192 thr) ==========
__global__ void k_xs(const float* __restrict__ x) {
    int n = blockIdx.x;
    __shared__ float inv;
    if (threadIdx.x == 0) {
        float s = 0.f;
#pragma unroll
        for (int p = 0; p < 8; ++p) s += g_rspart[p * NV + n];
        inv = 1.0f / s;
    }
    __syncthreads();
    int r = threadIdx.x;                 // bct
    int bc = r / TV, t = r - bc * TV;
    g_xs[n * RV + r] = x[((size_t)bc * NV + n) * TV + t] * inv;
}

// ========== K4: split-K GEMM  part[s][r][m] = sum_{n in split} xs[n][r]*P[n][m] ==========
// grid (64 m-tiles, 4 k-splits), 256 threads. CTA tile 192x128, thread 6x16 (8 f32x2 col-pairs).
__global__ __launch_bounds__(256, 1) void k_gemm() {
    __shared__ float sA[16 * 192];       // xs chunk   [k][r] (contiguous copy)
    __shared__ ull   sB[16 * 64];        // P chunk    [k][m-pairs]

    int m0 = blockIdx.x * 128;
    int s  = blockIdx.y;
    int n0 = s * 2048;
    int tid = threadIdx.x;
    int ty = tid >> 3;                   // 0..31 -> rows ty*6..ty*6+5
    int tx = tid & 7;                    // 0..7  -> col-pairs j*8+tx

    ull acc[6][8];
#pragma unroll
    for (int i = 0; i < 6; ++i)
#pragma unroll
        for (int j = 0; j < 8; ++j) acc[i][j] = 0ull;

    for (int kc = 0; kc < 128; ++kc) {
        int kb = n0 + kc * 16;
#pragma unroll
        for (int s2 = 0; s2 < 12; ++s2) {
            int idx = tid + s2 * 256;    // 3072 floats, layout-identical copy
            sA[idx] = g_xs[(size_t)kb * RV + idx];
        }
#pragma unroll
        for (int s2 = 0; s2 < 4; ++s2) {
            int idx = tid + s2 * 256;    // 1024 ull
            int kk = idx >> 6, md = idx & 63;
            sB[idx] = *(const ull*)&g_P[(size_t)(kb + kk) * NV + m0 + md * 2];
        }
        __syncthreads();

#pragma unroll
        for (int k = 0; k < 16; ++k) {
            ull bv[8];
#pragma unroll
            for (int j = 0; j < 8; ++j) bv[j] = sB[k * 64 + j * 8 + tx];
#pragma unroll
            for (int i = 0; i < 6; ++i) {
                float av = sA[k * 192 + ty * 6 + i];
                ull a2 = pack2(av, av);
#pragma unroll
                for (int j = 0; j < 8; ++j) fma2(acc[i][j], a2, bv[j]);
            }
        }
        __syncthreads();
    }

#pragma unroll
    for (int i = 0; i < 6; ++i) {
        int r = ty * 6 + i;
#pragma unroll
        for (int j = 0; j < 8; ++j) {
            size_t off = ((size_t)s * RV + r) * NV + m0 + (j * 8 + tx) * 2;
            *(ull*)&g_part[off] = acc[i][j];
        }
    }
}

// ========== K5: reduce 4 split-K partials, scatter to out[b][c][m][t] ==========
__global__ void k_out(float* __restrict__ out) {
    int idx = blockIdx.x * 256 + threadIdx.x;   // over RV*NV
    if (idx >= RV * NV) return;
    int r = idx >> 13;                           // /NV
    int m = idx & (NV - 1);
    const size_t st = (size_t)RV * NV;
    float v = g_part[idx] + g_part[st + idx] + g_part[2 * st + idx] + g_part[3 * st + idx];
    int bc = r / TV, t = r - bc * TV;
    out[((size_t)bc * NV + m) * TV + t] = v;
}

extern "C" void kernel_launch(void* const* d_in, const int* in_sizes, int n_in,
                              void* d_out, int out_size) {
    const float* x    = (const float*)d_in[0];
    const float* nv1  = (const float*)d_in[1];
    const float* nv2  = (const float*)d_in[2];
    const float* tvv  = (const float*)d_in[3];
    const float* kk   = (const float*)d_in[4];
    const int*   tind = (const int*)d_in[5];
    float* out = (float*)d_out;

    k_core<<<1, 1024>>>(tvv, kk, tind);
    k_amat<<<NV / 8, 256>>>(nv1);
    k_padj<<<dim3(8, 64), 256>>>(nv2);
    k_xs<<<NV, RV>>>(x);
    k_gemm<<<dim3(64, 4), 256>>>();
    k_out<<<(RV * NV + 255) / 256, 256>>>(out);
}

// round 4
// speedup vs baseline: 2.1844x; 2.1844x over previous
#include <cuda_runtime.h>
#include <cuda_bf16.h>
#include <cstdint>

#define NV 8192
#define DV 32
#define TV 12
#define RV 192   /* B*C*T = 2*8*12 */

typedef unsigned long long ull;

// ---------------- device scratch (no cudaMalloc anywhere) ----------------
__device__ float    g_core[DV * DV];
__device__ float    g_aT[DV * NV];                    // a transposed [f][n]
__device__ uint32_t g_Pth32[(size_t)NV * NV / 2];     // Pt hi bf16 pairs [m][n], 128MB
__device__ uint32_t g_Ptl32[(size_t)NV * NV / 2];     // Pt lo bf16 pairs, 128MB
__device__ uint32_t g_Bh32[NV * 96];                  // xs hi bf16 pairs [n][r]
__device__ uint32_t g_Bl32[NV * 96];                  // xs lo bf16 pairs [n][r]
__device__ float    g_cspart[64 * NV];                // column-sum partials per m-block
__device__ float    g_rinv[NV];                       // 1/rowsum
__device__ float    g_part2[2ULL * NV * RV];          // split-k partials fp32

// ---------------- f32x2 helpers ----------------
__device__ __forceinline__ ull pack2(float lo, float hi) {
    ull r; asm("mov.b64 %0, {%1,%2};" : "=l"(r) : "f"(lo), "f"(hi)); return r;
}
__device__ __forceinline__ void fma2(ull &acc, ull a, ull b) {
    asm("fma.rn.f32x2 %0, %1, %2, %0;" : "+l"(acc) : "l"(a), "l"(b));
}
__device__ __forceinline__ float2 unpack2(ull v) {
    float lo, hi; asm("mov.b64 {%0,%1}, %2;" : "=f"(lo), "=f"(hi) : "l"(v));
    return make_float2(lo, hi);
}

// ---------------- mma / ldmatrix / cp.async helpers (plain sm_80+ PTX) ----------------
__device__ __forceinline__ uint32_t smem_u32(const void* p) {
    uint32_t a;
    asm("{ .reg .u64 t; cvta.to.shared.u64 t, %1; cvt.u32.u64 %0, t; }" : "=r"(a) : "l"(p));
    return a;
}
__device__ __forceinline__ void ldsm_x4(uint32_t &r0, uint32_t &r1, uint32_t &r2, uint32_t &r3,
                                        uint32_t a) {
    asm volatile("ldmatrix.sync.aligned.m8n8.x4.shared.b16 {%0,%1,%2,%3}, [%4];"
                 : "=r"(r0), "=r"(r1), "=r"(r2), "=r"(r3) : "r"(a));
}
__device__ __forceinline__ void ldsm_x2t(uint32_t &r0, uint32_t &r1, uint32_t a) {
    asm volatile("ldmatrix.sync.aligned.m8n8.x2.trans.shared.b16 {%0,%1}, [%2];"
                 : "=r"(r0), "=r"(r1) : "r"(a));
}
__device__ __forceinline__ void mma16816(float* c, uint32_t a0, uint32_t a1, uint32_t a2,
                                         uint32_t a3, uint32_t b0, uint32_t b1) {
    asm volatile(
        "mma.sync.aligned.m16n8k16.row.col.f32.bf16.bf16.f32 "
        "{%0,%1,%2,%3}, {%4,%5,%6,%7}, {%8,%9}, {%0,%1,%2,%3};"
        : "+f"(c[0]), "+f"(c[1]), "+f"(c[2]), "+f"(c[3])
        : "r"(a0), "r"(a1), "r"(a2), "r"(a3), "r"(b0), "r"(b1));
}
__device__ __forceinline__ void cp16(uint32_t d, const void* s) {
    asm volatile("cp.async.cg.shared.global [%0], [%1], 16;" :: "r"(d), "l"(s) : "memory");
}

// ========== K1a: core[e][f] = sum_d tv[d]*k[d][e][f] ==========
__global__ void k_core(const float* __restrict__ timevec, const float* __restrict__ kk,
                       const int* __restrict__ tind) {
    int e = threadIdx.x >> 5, f = threadIdx.x & 31;
    int ti = tind[0];
    float s = 0.f;
#pragma unroll
    for (int d = 0; d < DV; ++d) s += timevec[ti * DV + d] * kk[(d * DV + e) * DV + f];
    g_core[e * DV + f] = s;
}

// ========== K1b: aT[f][n] = sum_e nv1[n][e]*core[e][f] ==========
__global__ void k_amat(const float* __restrict__ nv1) {
    __shared__ float sc[DV * DV];
    int tid = threadIdx.x;
    for (int i = tid; i < DV * DV; i += 256) sc[i] = g_core[i];
    __syncthreads();
    int n = blockIdx.x * 8 + (tid >> 5);
    int f = tid & 31;
    float s = 0.f;
#pragma unroll
    for (int e = 0; e < DV; ++e) s += nv1[n * DV + e] * sc[e * DV + f];
    g_aT[f * NV + n] = s;
}

// ========== K2: Pt[m][n] = exp(relu(nv2_m . a_n)) as bf16 hi/lo; colsum partials ==========
__global__ __launch_bounds__(256) void k_padj(const float* __restrict__ nv2) {
    __shared__ float sA[128 * 33];
    __shared__ ull   sB[32 * 66];
    __shared__ float red[16 * 132];

    int tid = threadIdx.x;
    int row0 = blockIdx.y * 128;
    int strip = blockIdx.x;
    for (int idx = tid; idx < 128 * 32; idx += 256) {
        int r = idx >> 5, c = idx & 31;
        sA[r * 33 + c] = nv2[(row0 + r) * DV + c];
    }
    int ty = tid >> 4, tx = tid & 15;

    for (int mc = 0; mc < 8; ++mc) {
        int n0c = strip * 1024 + mc * 128;
        __syncthreads();
        for (int idx = tid; idx < 32 * 64; idx += 256) {
            int k = idx >> 6, cp = idx & 63;
            sB[k * 66 + cp] = *(const ull*)&g_aT[k * NV + n0c + cp * 2];
        }
        __syncthreads();

        ull acc[8][4];
#pragma unroll
        for (int i = 0; i < 8; ++i)
#pragma unroll
            for (int j = 0; j < 4; ++j) acc[i][j] = 0ull;

#pragma unroll
        for (int k = 0; k < 32; ++k) {
            ull bv[4];
#pragma unroll
            for (int j = 0; j < 4; ++j) bv[j] = sB[k * 66 + j * 16 + tx];
#pragma unroll
            for (int i = 0; i < 8; ++i) {
                float av = sA[(ty * 8 + i) * 33 + k];
                ull a2 = pack2(av, av);
#pragma unroll
                for (int j = 0; j < 4; ++j) fma2(acc[i][j], a2, bv[j]);
            }
        }

        float rs0[4] = {0, 0, 0, 0}, rs1[4] = {0, 0, 0, 0};
#pragma unroll
        for (int i = 0; i < 8; ++i) {
            int m = row0 + ty * 8 + i;
#pragma unroll
            for (int j = 0; j < 4; ++j) {
                float2 h = unpack2(acc[i][j]);
                float p0 = __expf(fmaxf(h.x, 0.f));
                float p1 = __expf(fmaxf(h.y, 0.f));
                rs0[j] += p0; rs1[j] += p1;
                __nv_bfloat162 hh = __float22bfloat162_rn(make_float2(p0, p1));
                uint32_t hw = *(uint32_t*)&hh;
                float l0 = p0 - __uint_as_float(hw << 16);
                float l1 = p1 - __uint_as_float(hw & 0xFFFF0000u);
                __nv_bfloat162 lp = __float22bfloat162_rn(make_float2(l0, l1));
                size_t wi = ((size_t)m * NV + n0c + j * 32 + tx * 2) >> 1;
                g_Pth32[wi] = hw;
                g_Ptl32[wi] = *(uint32_t*)&lp;
            }
        }
#pragma unroll
        for (int j = 0; j < 4; ++j)
            *(float2*)&red[ty * 132 + j * 32 + tx * 2] = make_float2(rs0[j], rs1[j]);
        __syncthreads();
        if (tid < 128) {
            float s = 0.f;
#pragma unroll
            for (int q = 0; q < 16; ++q) s += red[q * 132 + tid];
            g_cspart[blockIdx.y * NV + n0c + tid] = s;
        }
    }
}

// ========== K2b: rowsum reduce (coalesced over n) ==========
__global__ void k_rsum() {
    int n = blockIdx.x * 256 + threadIdx.x;
    float s = 0.f;
#pragma unroll
    for (int mb = 0; mb < 64; ++mb) s += g_cspart[mb * NV + n];
    g_rinv[n] = 1.0f / s;
}

// ========== K3: B[n][r] = x[bc][n][t] * rinv[n] as bf16 hi/lo ==========
__global__ __launch_bounds__(96) void k_xs(const float* __restrict__ x) {
    int n = blockIdx.x;
    int tid = threadIdx.x;                // 0..95, r pair = (2t, 2t+1)
    float inv = g_rinv[n];
    int r0 = tid * 2;
    int bc = r0 / TV, t = r0 - bc * TV;   // t even -> t+1 in same bc
    const float* xp = x + ((size_t)bc * NV + n) * TV + t;
    float v0 = xp[0] * inv, v1 = xp[1] * inv;
    __nv_bfloat162 hh = __float22bfloat162_rn(make_float2(v0, v1));
    uint32_t hw = *(uint32_t*)&hh;
    float l0 = v0 - __uint_as_float(hw << 16);
    float l1 = v1 - __uint_as_float(hw & 0xFFFF0000u);
    __nv_bfloat162 lp = __float22bfloat162_rn(make_float2(l0, l1));
    g_Bh32[n * 96 + tid] = hw;
    g_Bl32[n * 96 + tid] = *(uint32_t*)&lp;
}

// ========== K4: warp-mma bf16 split GEMM  C[m][r] = sum_n Pt[m][n]*xs[n][r] ==========
// CTA: 128m x 192r, split-K 2 (4096 n each). 384 thr = 12 warps (2m x 6n).
// k-chunk 64, double-buffered cp.async. 3-product hi/lo split.
#define A_OFF_LO 16384
#define B_OFF    32768
#define B_STRIDE 400
#define B_OFF_LO 25600
#define BUFB     83968
#define SMEM_DYN (2 * BUFB)

__device__ __forceinline__ void gemm_loadbuf(uint32_t sbase, int buf, int i0, size_t kg,
                                             int tid) {
    uint32_t A = sbase + buf * BUFB;
    uint32_t B = A + B_OFF;
    const char* pa = (const char*)g_Pth32;
    const char* pl = (const char*)g_Ptl32;
#pragma unroll
    for (int l = 0; l < 6; ++l) {
        int idx = tid + l * 384;
        if (idx < 2048) {
            int half = idx >> 10, j = idx & 1023;
            int row = j >> 3, kb = j & 7;
            const char* src = (half ? pl : pa) + ((size_t)(i0 + row) * NV + kg + kb * 8) * 2;
            uint32_t dst = A + half * A_OFF_LO + row * 128 + ((kb ^ (row & 7)) << 4);
            cp16(dst, src);
        }
    }
    const char* bh = (const char*)g_Bh32;
    const char* bl = (const char*)g_Bl32;
#pragma unroll
    for (int l = 0; l < 8; ++l) {
        int idx = tid + l * 384;
        int half = idx >= 1536;
        int j = half ? idx - 1536 : idx;
        int kr = j / 24, cb = j % 24;
        const char* src = (half ? bl : bh) + (kg + kr) * 384 + cb * 16;
        uint32_t dst = B + half * B_OFF_LO + kr * B_STRIDE + cb * 16;
        cp16(dst, src);
    }
    asm volatile("cp.async.commit_group;" ::: "memory");
}

__global__ __launch_bounds__(384, 1) void k_gemm3() {
    extern __shared__ char sm[];
    uint32_t sbase = smem_u32(sm);
    const int tid = threadIdx.x, lane = tid & 31, wid = tid >> 5;
    const int wm = wid & 1;          // 64-row half
    const int wn = wid >> 1;         // 0..5 -> 32-col slice
    const int i0 = blockIdx.x * 128;
    const size_t k0 = (size_t)blockIdx.y * 4096;

    float acc[4][4][4];
#pragma unroll
    for (int mt = 0; mt < 4; ++mt)
#pragma unroll
        for (int nt = 0; nt < 4; ++nt)
#pragma unroll
            for (int q = 0; q < 4; ++q) acc[mt][nt][q] = 0.f;

    gemm_loadbuf(sbase, 0, i0, k0, tid);

    for (int c = 0; c < 64; ++c) {
        int buf = c & 1;
        if (c + 1 < 64) {
            gemm_loadbuf(sbase, buf ^ 1, i0, k0 + (size_t)(c + 1) * 64, tid);
            asm volatile("cp.async.wait_group 1;" ::: "memory");
        } else {
            asm volatile("cp.async.wait_group 0;" ::: "memory");
        }
        __syncthreads();

        uint32_t A = sbase + buf * BUFB;
        uint32_t B = A + B_OFF;
#pragma unroll
        for (int ks = 0; ks < 4; ++ks) {
            uint32_t bh[4][2], blo[4][2];
            int krow = ks * 16 + (lane & 15);
#pragma unroll
            for (int nt = 0; nt < 4; ++nt) {
                uint32_t ba = B + krow * B_STRIDE + (wn * 32 + nt * 8) * 2;
                ldsm_x2t(bh[nt][0], bh[nt][1], ba);
                ldsm_x2t(blo[nt][0], blo[nt][1], ba + B_OFF_LO);
            }
            int row = wm * 64 + (lane & 15);
            int kb = ks * 2 + (lane >> 4);
#pragma unroll
            for (int mt = 0; mt < 4; ++mt) {
                int rr = row + mt * 16;
                uint32_t aa = A + rr * 128 + ((kb ^ (rr & 7)) << 4);
                uint32_t ah0, ah1, ah2, ah3, al0, al1, al2, al3;
                ldsm_x4(ah0, ah1, ah2, ah3, aa);
                ldsm_x4(al0, al1, al2, al3, aa + A_OFF_LO);
#pragma unroll
                for (int nt = 0; nt < 4; ++nt) {
                    mma16816(acc[mt][nt], ah0, ah1, ah2, ah3, bh[nt][0], bh[nt][1]);
                    mma16816(acc[mt][nt], ah0, ah1, ah2, ah3, blo[nt][0], blo[nt][1]);
                    mma16816(acc[mt][nt], al0, al1, al2, al3, bh[nt][0], bh[nt][1]);
                }
            }
        }
        __syncthreads();
    }

    float* outp = g_part2 + (size_t)blockIdx.y * NV * RV;
#pragma unroll
    for (int mt = 0; mt < 4; ++mt) {
#pragma unroll
        for (int nt = 0; nt < 4; ++nt) {
            int m = i0 + wm * 64 + mt * 16 + (lane >> 2);
            int r = wn * 32 + nt * 8 + (lane & 3) * 2;
            *(float2*)&outp[(size_t)m * RV + r] = make_float2(acc[mt][nt][0], acc[mt][nt][1]);
            *(float2*)&outp[(size_t)(m + 8) * RV + r] = make_float2(acc[mt][nt][2], acc[mt][nt][3]);
        }
    }
}

// ========== K5: reduce 2 split-K partials, scatter to out[b][c][m][t] ==========
__global__ void k_out2(float* __restrict__ out) {
    int idx = blockIdx.x * 256 + threadIdx.x;
    if (idx >= NV * RV) return;
    int m = idx / RV, r = idx - m * RV;
    float v = g_part2[idx] + g_part2[(size_t)NV * RV + idx];
    int bc = r / TV, t = r - bc * TV;
    out[((size_t)bc * NV + m) * TV + t] = v;
}

extern "C" void kernel_launch(void* const* d_in, const int* in_sizes, int n_in,
                              void* d_out, int out_size) {
    const float* x    = (const float*)d_in[0];
    const float* nv1  = (const float*)d_in[1];
    const float* nv2  = (const float*)d_in[2];
    const float* tvv  = (const float*)d_in[3];
    const float* kk   = (const float*)d_in[4];
    const int*   tind = (const int*)d_in[5];
    float* out = (float*)d_out;

    cudaFuncSetAttribute(k_gemm3, cudaFuncAttributeMaxDynamicSharedMemorySize, SMEM_DYN);

    k_core<<<1, 1024>>>(tvv, kk, tind);
    k_amat<<<NV / 8, 256>>>(nv1);
    k_padj<<<dim3(8, 64), 256>>>(nv2);
    k_rsum<<<NV / 256, 256>>>();
    k_xs<<<NV, 96>>>(x);
    k_gemm3<<<dim3(64, 2), 384, SMEM_DYN>>>();
    k_out2<<<(NV * RV + 255) / 256, 256>>>(out);
}